// round 16
// baseline (speedup 1.0000x reference)
#include <cuda_runtime.h>
#include <math.h>
#include <float.h>

// AUAvULoss: N=65536 rows, C=1000 classes fp32 logits, int64 labels.
//  k_rows_spec: one warp/row, C==1000, branch-free (sentinel last chunk).
//               R13/R15-exact body (best measured: 44.7us, DRAM 75.4%).
//  k_mm:   64-block reduce, vectorized float4 loads (R15-exact).
//  k_bins: 64 blocks x 256 threads x 4 elems (float4 loads) — 4x fewer
//          ticket/bin-merge atomics; last block computes scalar + re-zeroes.
//  Tail kernels launched with PDL (programmatic stream serialization).

#define MAXN 65536
#define MMGRID 64
#define BINGRID 64
#define LOG2E 1.4426950408889634f
#define LN2   0.6931471805599453f

__device__ float g_unc[MAXN];
__device__ float g_confacc[MAXN];   // +conf if accurate, -conf if not
__device__ float g_ce[MAXN];
__device__ float g_pmin[MMGRID];
__device__ float g_pmax[MMGRID];
__device__ float g_pce[MMGRID];
__device__ float g_bins[88];        // zero at load; last block re-zeroes
__device__ unsigned int g_done;     // monotonic; tested modulo gridDim

// ---------------- K1 specialized: C == 1000 (chunks = 250) ----------------
template <int WPB>
__global__ void __launch_bounds__(WPB * 32)
k_rows_spec(const float* __restrict__ logits,
            const long long* __restrict__ labels,
            int n) {
    constexpr int C = 1000;
    const int warp = blockIdx.x * WPB + (threadIdx.x >> 5);
    if (warp >= n) return;
    const int row  = warp;
    const int lane = threadIdx.x & 31;
    const float4* __restrict__ rp =
        reinterpret_cast<const float4*>(logits + (size_t)row * (size_t)C);

    // 7 unconditional chunks + 1 predicated chunk with inert sentinel.
    float4 v[8];
    #pragma unroll
    for (int k = 0; k < 7; k++) v[k] = rp[lane + (k << 5)];
    v[7] = make_float4(-1e30f, -1e30f, -1e30f, -1e30f);
    if (lane < 26) v[7] = rp[lane + 224];

    // max + first-index argmax, fully unconditional
    float m = -FLT_MAX;
    int mi = 0x7FFFFFFF;
    #pragma unroll
    for (int k = 0; k < 8; k++) {
        const int base = (lane + (k << 5)) << 2;
        if (v[k].x > m) { m = v[k].x; mi = base; }
        if (v[k].y > m) { m = v[k].y; mi = base + 1; }
        if (v[k].z > m) { m = v[k].z; mi = base + 2; }
        if (v[k].w > m) { m = v[k].w; mi = base + 3; }
    }
    #pragma unroll
    for (int o = 16; o > 0; o >>= 1) {
        float om = __shfl_xor_sync(0xffffffffu, m, o);
        int   oi = __shfl_xor_sync(0xffffffffu, mi, o);
        if (om > m || (om == m && oi < mi)) { m = om; mi = oi; }
    }
    const float rm = m;
    const int pred = mi;

    // exp pass, log2 domain, fully unconditional
    const float nc = -rm * LOG2E;
    float S = 0.0f, T2 = 0.0f;
    #pragma unroll
    for (int k = 0; k < 8; k++) {
        float t, e;
        t = fmaf(v[k].x, LOG2E, nc); e = exp2f(t); S += e; T2 = fmaf(t, e, T2);
        t = fmaf(v[k].y, LOG2E, nc); e = exp2f(t); S += e; T2 = fmaf(t, e, T2);
        t = fmaf(v[k].z, LOG2E, nc); e = exp2f(t); S += e; T2 = fmaf(t, e, T2);
        t = fmaf(v[k].w, LOG2E, nc); e = exp2f(t); S += e; T2 = fmaf(t, e, T2);
    }
    #pragma unroll
    for (int o = 16; o > 0; o >>= 1) {
        S  += __shfl_xor_sync(0xffffffffu, S, o);
        T2 += __shfl_xor_sync(0xffffffffu, T2, o);
    }

    if (lane == 0) {
        int lbl = (int)labels[row];
        float zl = __ldg(&logits[(size_t)row * (size_t)C + lbl]); // L1 hit
        float conf = 1.0f / S;
        float logS = logf(S);
        float unc  = logS - (T2 * LN2) / S;     // entropy
        float ce   = (rm - zl) + logS;          // -log_softmax at label
        g_unc[row]     = unc;
        g_confacc[row] = (pred == lbl) ? conf : -conf;
        g_ce[row]      = ce;
    }
}

// ---------------- K1 generic fallback ----------------
template <int WPB>
__global__ void __launch_bounds__(WPB * 32)
k_rows_gen(const float* __restrict__ logits,
           const long long* __restrict__ labels,
           int C, int n) {
    const int warp = blockIdx.x * WPB + (threadIdx.x >> 5);
    if (warp >= n) return;
    const int row  = warp;
    const int lane = threadIdx.x & 31;
    const int chunks = (C + 3) >> 2;
    const float4* __restrict__ rp =
        reinterpret_cast<const float4*>(logits + (size_t)row * (size_t)C);

    float4 v[8];
    bool   ok[8];
    #pragma unroll
    for (int k = 0; k < 8; k++) {
        int c = lane + (k << 5);
        ok[k] = (c < chunks);
        if (ok[k]) v[k] = rp[c];
    }
    float m = -FLT_MAX;
    int mi = 0x7FFFFFFF;
    #pragma unroll
    for (int k = 0; k < 8; k++) {
        if (ok[k]) {
            int base = (lane + (k << 5)) << 2;
            if (v[k].x > m) { m = v[k].x; mi = base; }
            if (v[k].y > m) { m = v[k].y; mi = base + 1; }
            if (v[k].z > m) { m = v[k].z; mi = base + 2; }
            if (v[k].w > m) { m = v[k].w; mi = base + 3; }
        }
    }
    #pragma unroll
    for (int o = 16; o > 0; o >>= 1) {
        float om = __shfl_xor_sync(0xffffffffu, m, o);
        int   oi = __shfl_xor_sync(0xffffffffu, mi, o);
        if (om > m || (om == m && oi < mi)) { m = om; mi = oi; }
    }
    const float rm = m;
    const int pred = mi;
    const float nc = -rm * LOG2E;
    float S = 0.0f, T2 = 0.0f;
    #pragma unroll
    for (int k = 0; k < 8; k++) {
        if (ok[k]) {
            float t, e;
            t = fmaf(v[k].x, LOG2E, nc); e = exp2f(t); S += e; T2 = fmaf(t, e, T2);
            t = fmaf(v[k].y, LOG2E, nc); e = exp2f(t); S += e; T2 = fmaf(t, e, T2);
            t = fmaf(v[k].z, LOG2E, nc); e = exp2f(t); S += e; T2 = fmaf(t, e, T2);
            t = fmaf(v[k].w, LOG2E, nc); e = exp2f(t); S += e; T2 = fmaf(t, e, T2);
        }
    }
    #pragma unroll
    for (int o = 16; o > 0; o >>= 1) {
        S  += __shfl_xor_sync(0xffffffffu, S, o);
        T2 += __shfl_xor_sync(0xffffffffu, T2, o);
    }
    if (lane == 0) {
        int lbl = (int)labels[row];
        float zl = __ldg(&logits[(size_t)row * (size_t)C + lbl]);
        float conf = 1.0f / S;
        float logS = logf(S);
        g_unc[row]     = logS - (T2 * LN2) / S;
        g_confacc[row] = (pred == lbl) ? conf : -conf;
        g_ce[row]      = (rm - zl) + logS;
    }
}

// ---------------- K2: 64-block minmax + ce reduce (vectorized, PDL) ----------------
template <int BLK>
__global__ void __launch_bounds__(BLK)
k_mm(int n) {
    const int tid  = threadIdx.x;
    const int lane = tid & 31;
    const int wid  = tid >> 5;

    // PDL: wait for k_rows to fully complete before reading its outputs.
    cudaGridDependencySynchronize();

    const int nv4 = n >> 2;
    const float4* __restrict__ u4 = reinterpret_cast<const float4*>(g_unc);
    const float4* __restrict__ c4 = reinterpret_cast<const float4*>(g_ce);

    float mn = FLT_MAX, mx = -FLT_MAX, cs = 0.0f;
    for (int i = blockIdx.x * BLK + tid; i < nv4; i += MMGRID * BLK) {
        float4 u = u4[i];
        float4 c = c4[i];
        mn = fminf(mn, fminf(fminf(u.x, u.y), fminf(u.z, u.w)));
        mx = fmaxf(mx, fmaxf(fmaxf(u.x, u.y), fmaxf(u.z, u.w)));
        cs += (c.x + c.y) + (c.z + c.w);
    }
    // scalar tail (n % 4), handled by block 0 / thread 0
    if (blockIdx.x == 0 && tid == 0) {
        for (int i = nv4 << 2; i < n; i++) {
            float u = g_unc[i];
            mn = fminf(mn, u);
            mx = fmaxf(mx, u);
            cs += g_ce[i];
        }
    }
    #pragma unroll
    for (int o = 16; o > 0; o >>= 1) {
        mn = fminf(mn, __shfl_xor_sync(0xffffffffu, mn, o));
        mx = fmaxf(mx, __shfl_xor_sync(0xffffffffu, mx, o));
        cs += __shfl_xor_sync(0xffffffffu, cs, o);
    }
    __shared__ float sm[BLK / 32], sx[BLK / 32], sc[BLK / 32];
    if (lane == 0) { sm[wid] = mn; sx[wid] = mx; sc[wid] = cs; }
    __syncthreads();
    if (tid == 0) {
        for (int w = 1; w < BLK / 32; w++) {
            mn = fminf(mn, sm[w]);
            mx = fmaxf(mx, sx[w]);
            cs += sc[w];
        }
        g_pmin[blockIdx.x] = mn;
        g_pmax[blockIdx.x] = mx;
        g_pce[blockIdx.x]  = cs;
    }
}

// ---------------- K3: histogram (4 elems/thread) + fused final (PDL) ----------------
template <int BLK>
__global__ void __launch_bounds__(BLK)
k_bins(float* __restrict__ out, int n) {
    __shared__ float sb[88];
    __shared__ float s_red[2 * (BLK / 32)];
    __shared__ float s_bcast[2];
    __shared__ bool  is_last;

    const int tid  = threadIdx.x;
    const int lane = tid & 31;
    const int wid  = tid >> 5;

    if (tid < 88) sb[tid] = 0.0f;

    // PDL: wait for k_mm (and transitively k_rows) before reading.
    cudaGridDependencySynchronize();

    // phase A: reduce the 64 partials
    float mn = (tid < MMGRID) ? g_pmin[tid] : FLT_MAX;
    float mx = (tid < MMGRID) ? g_pmax[tid] : -FLT_MAX;
    #pragma unroll
    for (int o = 16; o > 0; o >>= 1) {
        mn = fminf(mn, __shfl_xor_sync(0xffffffffu, mn, o));
        mx = fmaxf(mx, __shfl_xor_sync(0xffffffffu, mx, o));
    }
    if (lane == 0) { s_red[wid] = mn; s_red[wid + BLK / 32] = mx; }
    __syncthreads();
    if (tid == 0) {
        s_bcast[0] = fminf(s_red[0], s_red[1]);          // warps 0,1 cover tid<64
        s_bcast[1] = fmaxf(s_red[BLK / 32], s_red[BLK / 32 + 1]);
    }
    __syncthreads();
    const float umin  = s_bcast[0];
    const float range = s_bcast[1] - umin;

    // phase B: 4 elements per thread, vectorized when fully in range
    const int base = (blockIdx.x * BLK + tid) << 2;
    float uq[4], cq[4];
    int nval = 0;
    if (base + 3 < n) {
        float4 u = *reinterpret_cast<const float4*>(&g_unc[base]);
        float4 c = *reinterpret_cast<const float4*>(&g_confacc[base]);
        uq[0] = u.x; uq[1] = u.y; uq[2] = u.z; uq[3] = u.w;
        cq[0] = c.x; cq[1] = c.y; cq[2] = c.z; cq[3] = c.w;
        nval = 4;
    } else if (base < n) {
        nval = n - base;
        for (int j = 0; j < nval; j++) {
            uq[j] = g_unc[base + j];
            cq[j] = g_confacc[base + j];
        }
    }
    for (int j = 0; j < nval; j++) {
        float unc = uq[j];
        float ca  = cq[j];
        int acc   = (ca > 0.0f) ? 1 : 0;
        float conf = fabsf(ca);
        float w = acc ? conf : (1.0f - conf);
        float t = 1.0f - 2.0f / (__expf(2.0f * unc) + 1.0f);   // tanh(u), u>=0
        float bc = w * (1.0f - t);
        float bu = w * t;
        int j0 = 21;
        #pragma unroll
        for (int jj = 20; jj >= 0; jj--) {
            float thv = umin + (0.05f * (float)jj) * range;
            if (unc <= thv) j0 = jj;
        }
        atomicAdd(&sb[acc * 44 + j0], bc);
        atomicAdd(&sb[acc * 44 + 22 + j0], bu);
    }
    __syncthreads();
    if (tid < 88) {
        float v = sb[tid];
        if (v != 0.0f) atomicAdd(&g_bins[tid], v);   // 88 spread addresses
    }

    // last-block election (monotonic counter; 2^32 % 64 == 0 -> replay-safe)
    __threadfence();
    if (tid == 0) {
        unsigned int d = atomicAdd(&g_done, 1u);
        is_last = (d % gridDim.x == gridDim.x - 1);
    }
    __syncthreads();
    if (!is_last) return;

    __shared__ float fb[88];
    __shared__ float s_cs;
    if (tid < 88) {
        fb[tid] = g_bins[tid];
        g_bins[tid] = 0.0f;                  // leave zeroed for next replay
    }
    if (tid == 0) {
        float cs = 0.0f;
        for (int b = 0; b < MMGRID; b++) cs += g_pce[b];
        s_cs = cs;
    }
    __syncthreads();

    if (tid == 0) {
        float au_rem = 0.0f, iu_rem = 0.0f;
        for (int k = 0; k < 22; k++) {
            au_rem += fb[66 + k];   // acc=1, kind=U
            iu_rem += fb[22 + k];   // acc=0, kind=U
        }
        float nac = 0.0f, nic = 0.0f;
        float avu[21];
        for (int j = 0; j < 21; j++) {
            nac    += fb[44 + j];   // acc=1, kind=C prefix
            nic    += fb[j];        // acc=0, kind=C prefix
            au_rem -= fb[66 + j];
            iu_rem -= fb[22 + j];
            avu[j] = (nac + iu_rem) / (nac + au_rem + nic + iu_rem + 1e-12f);
        }
        float auc = 0.0f;
        for (int j = 0; j < 20; j++) auc += (avu[j + 1] + avu[j]);
        auc *= 0.5f * 0.05f;
        out[0] = -3.0f * logf(auc + 1e-12f) + s_cs / (float)n;
    }
}

extern "C" void kernel_launch(void* const* d_in, const int* in_sizes, int n_in,
                              void* d_out, int out_size) {
    const float*     logits = (const float*)d_in[0];
    const long long* labels = (const long long*)d_in[1];
    int n = in_sizes[1];
    int C = in_sizes[0] / n;

    const int WPB = 8;
    if (C == 1000) {
        k_rows_spec<WPB><<<(n + WPB - 1) / WPB, WPB * 32>>>(logits, labels, n);
    } else {
        k_rows_gen<WPB><<<(n + WPB - 1) / WPB, WPB * 32>>>(logits, labels, C, n);
    }

    cudaLaunchAttribute pdl[1];
    pdl[0].id = cudaLaunchAttributeProgrammaticStreamSerialization;
    pdl[0].val.programmaticStreamSerializationAllowed = 1;

    {
        cudaLaunchConfig_t cfg = {};
        cfg.gridDim  = dim3(MMGRID, 1, 1);
        cfg.blockDim = dim3(256, 1, 1);
        cfg.attrs = pdl;
        cfg.numAttrs = 1;
        cudaLaunchKernelEx(&cfg, k_mm<256>, n);
    }
    {
        unsigned bg = (unsigned)((n + 1023) / 1024);   // 4 elems/thread, 256 thr
        cudaLaunchConfig_t cfg = {};
        cfg.gridDim  = dim3(bg, 1, 1);
        cfg.blockDim = dim3(256, 1, 1);
        cfg.attrs = pdl;
        cfg.numAttrs = 1;
        cudaLaunchKernelEx(&cfg, k_bins<256>, (float*)d_out, n);
    }
}

// round 17
// speedup vs baseline: 1.1026x; 1.1026x over previous
#include <cuda_runtime.h>
#include <math.h>
#include <float.h>

// AUAvULoss: N=65536 rows, C=1000 classes fp32 logits, int64 labels.
// FINAL (R13): best of 16 measured variants.
//  k_rows_spec: one warp/row, C==1000, branch-free (sentinel last chunk),
//               log2-domain exp pass. 44.7-44.9us, DRAM 75% of spec
//               (= measured read-once LTS ceiling for this access shape).
//  k_mm:   64-block parallel reduce -> g_pmin/g_pmax/g_pce[64]
//  k_bins: reduce 64 partials, bin 1 elem/thread, atomicAdd into g_bins;
//          last block (monotonic counter) computes scalar + re-zeroes bins.
//  Tail kernels launched with PDL (programmatic stream serialization).

#define MAXN 65536
#define MMGRID 64
#define LOG2E 1.4426950408889634f
#define LN2   0.6931471805599453f

__device__ float g_unc[MAXN];
__device__ float g_confacc[MAXN];   // +conf if accurate, -conf if not
__device__ float g_ce[MAXN];
__device__ float g_pmin[MMGRID];
__device__ float g_pmax[MMGRID];
__device__ float g_pce[MMGRID];
__device__ float g_bins[88];        // zero at load; last block re-zeroes
__device__ unsigned int g_done;     // monotonic; tested modulo gridDim

// ---------------- K1 specialized: C == 1000 (chunks = 250) ----------------
template <int WPB>
__global__ void __launch_bounds__(WPB * 32)
k_rows_spec(const float* __restrict__ logits,
            const long long* __restrict__ labels,
            int n) {
    constexpr int C = 1000;
    const int warp = blockIdx.x * WPB + (threadIdx.x >> 5);
    if (warp >= n) return;
    const int row  = warp;
    const int lane = threadIdx.x & 31;
    const float4* __restrict__ rp =
        reinterpret_cast<const float4*>(logits + (size_t)row * (size_t)C);

    // 7 unconditional chunks + 1 predicated chunk with inert sentinel.
    // Sentinel -1e30: loses all max compares; in the exp pass
    // t = fma(-1e30, log2e, nc) is finite -> exp2(t)=0 -> adds 0 to S,
    // and finite*0 = 0 -> adds 0 to T2 (no NaN: only inf*0 is NaN).
    float4 v[8];
    #pragma unroll
    for (int k = 0; k < 7; k++) v[k] = rp[lane + (k << 5)];
    v[7] = make_float4(-1e30f, -1e30f, -1e30f, -1e30f);
    if (lane < 26) v[7] = rp[lane + 224];

    // max + first-index argmax, fully unconditional
    float m = -FLT_MAX;
    int mi = 0x7FFFFFFF;
    #pragma unroll
    for (int k = 0; k < 8; k++) {
        const int base = (lane + (k << 5)) << 2;
        if (v[k].x > m) { m = v[k].x; mi = base; }
        if (v[k].y > m) { m = v[k].y; mi = base + 1; }
        if (v[k].z > m) { m = v[k].z; mi = base + 2; }
        if (v[k].w > m) { m = v[k].w; mi = base + 3; }
    }
    #pragma unroll
    for (int o = 16; o > 0; o >>= 1) {
        float om = __shfl_xor_sync(0xffffffffu, m, o);
        int   oi = __shfl_xor_sync(0xffffffffu, mi, o);
        if (om > m || (om == m && oi < mi)) { m = om; mi = oi; }
    }
    const float rm = m;
    const int pred = mi;

    // exp pass, log2 domain, fully unconditional
    const float nc = -rm * LOG2E;
    float S = 0.0f, T2 = 0.0f;
    #pragma unroll
    for (int k = 0; k < 8; k++) {
        float t, e;
        t = fmaf(v[k].x, LOG2E, nc); e = exp2f(t); S += e; T2 = fmaf(t, e, T2);
        t = fmaf(v[k].y, LOG2E, nc); e = exp2f(t); S += e; T2 = fmaf(t, e, T2);
        t = fmaf(v[k].z, LOG2E, nc); e = exp2f(t); S += e; T2 = fmaf(t, e, T2);
        t = fmaf(v[k].w, LOG2E, nc); e = exp2f(t); S += e; T2 = fmaf(t, e, T2);
    }
    #pragma unroll
    for (int o = 16; o > 0; o >>= 1) {
        S  += __shfl_xor_sync(0xffffffffu, S, o);
        T2 += __shfl_xor_sync(0xffffffffu, T2, o);
    }

    if (lane == 0) {
        int lbl = (int)labels[row];
        float zl = __ldg(&logits[(size_t)row * (size_t)C + lbl]); // L1 hit
        float conf = 1.0f / S;
        float logS = logf(S);
        float unc  = logS - (T2 * LN2) / S;     // entropy
        float ce   = (rm - zl) + logS;          // -log_softmax at label
        g_unc[row]     = unc;
        g_confacc[row] = (pred == lbl) ? conf : -conf;
        g_ce[row]      = ce;
    }
}

// ---------------- K1 generic fallback ----------------
template <int WPB>
__global__ void __launch_bounds__(WPB * 32)
k_rows_gen(const float* __restrict__ logits,
           const long long* __restrict__ labels,
           int C, int n) {
    const int warp = blockIdx.x * WPB + (threadIdx.x >> 5);
    if (warp >= n) return;
    const int row  = warp;
    const int lane = threadIdx.x & 31;
    const int chunks = (C + 3) >> 2;
    const float4* __restrict__ rp =
        reinterpret_cast<const float4*>(logits + (size_t)row * (size_t)C);

    float4 v[8];
    bool   ok[8];
    #pragma unroll
    for (int k = 0; k < 8; k++) {
        int c = lane + (k << 5);
        ok[k] = (c < chunks);
        if (ok[k]) v[k] = rp[c];
    }
    float m = -FLT_MAX;
    int mi = 0x7FFFFFFF;
    #pragma unroll
    for (int k = 0; k < 8; k++) {
        if (ok[k]) {
            int base = (lane + (k << 5)) << 2;
            if (v[k].x > m) { m = v[k].x; mi = base; }
            if (v[k].y > m) { m = v[k].y; mi = base + 1; }
            if (v[k].z > m) { m = v[k].z; mi = base + 2; }
            if (v[k].w > m) { m = v[k].w; mi = base + 3; }
        }
    }
    #pragma unroll
    for (int o = 16; o > 0; o >>= 1) {
        float om = __shfl_xor_sync(0xffffffffu, m, o);
        int   oi = __shfl_xor_sync(0xffffffffu, mi, o);
        if (om > m || (om == m && oi < mi)) { m = om; mi = oi; }
    }
    const float rm = m;
    const int pred = mi;
    const float nc = -rm * LOG2E;
    float S = 0.0f, T2 = 0.0f;
    #pragma unroll
    for (int k = 0; k < 8; k++) {
        if (ok[k]) {
            float t, e;
            t = fmaf(v[k].x, LOG2E, nc); e = exp2f(t); S += e; T2 = fmaf(t, e, T2);
            t = fmaf(v[k].y, LOG2E, nc); e = exp2f(t); S += e; T2 = fmaf(t, e, T2);
            t = fmaf(v[k].z, LOG2E, nc); e = exp2f(t); S += e; T2 = fmaf(t, e, T2);
            t = fmaf(v[k].w, LOG2E, nc); e = exp2f(t); S += e; T2 = fmaf(t, e, T2);
        }
    }
    #pragma unroll
    for (int o = 16; o > 0; o >>= 1) {
        S  += __shfl_xor_sync(0xffffffffu, S, o);
        T2 += __shfl_xor_sync(0xffffffffu, T2, o);
    }
    if (lane == 0) {
        int lbl = (int)labels[row];
        float zl = __ldg(&logits[(size_t)row * (size_t)C + lbl]);
        float conf = 1.0f / S;
        float logS = logf(S);
        g_unc[row]     = logS - (T2 * LN2) / S;
        g_confacc[row] = (pred == lbl) ? conf : -conf;
        g_ce[row]      = (rm - zl) + logS;
    }
}

// ---------------- K2: 64-block minmax + ce partial reduce (PDL) ----------------
template <int BLK>
__global__ void __launch_bounds__(BLK)
k_mm(int n) {
    const int tid  = threadIdx.x;
    const int lane = tid & 31;
    const int wid  = tid >> 5;

    // PDL: wait for k_rows to fully complete before reading its outputs.
    cudaGridDependencySynchronize();

    float mn = FLT_MAX, mx = -FLT_MAX, cs = 0.0f;
    for (int i = blockIdx.x * BLK + tid; i < n; i += MMGRID * BLK) {
        float u = g_unc[i];
        mn = fminf(mn, u);
        mx = fmaxf(mx, u);
        cs += g_ce[i];
    }
    #pragma unroll
    for (int o = 16; o > 0; o >>= 1) {
        mn = fminf(mn, __shfl_xor_sync(0xffffffffu, mn, o));
        mx = fmaxf(mx, __shfl_xor_sync(0xffffffffu, mx, o));
        cs += __shfl_xor_sync(0xffffffffu, cs, o);
    }
    __shared__ float sm[BLK / 32], sx[BLK / 32], sc[BLK / 32];
    if (lane == 0) { sm[wid] = mn; sx[wid] = mx; sc[wid] = cs; }
    __syncthreads();
    if (tid == 0) {
        for (int w = 1; w < BLK / 32; w++) {
            mn = fminf(mn, sm[w]);
            mx = fmaxf(mx, sx[w]);
            cs += sc[w];
        }
        g_pmin[blockIdx.x] = mn;
        g_pmax[blockIdx.x] = mx;
        g_pce[blockIdx.x]  = cs;
    }
}

// ---------------- K3: histogram + fused final scalar (PDL) ----------------
template <int BLK>
__global__ void __launch_bounds__(BLK)
k_bins(float* __restrict__ out, int n) {
    __shared__ float sb[88];
    __shared__ float s_red[2 * (BLK / 32)];
    __shared__ float s_bcast[2];
    __shared__ bool  is_last;

    const int tid  = threadIdx.x;
    const int lane = tid & 31;
    const int wid  = tid >> 5;

    if (tid < 88) sb[tid] = 0.0f;

    // PDL: wait for k_mm (and transitively k_rows) before reading.
    cudaGridDependencySynchronize();

    float mn = (tid < MMGRID) ? g_pmin[tid] : FLT_MAX;
    float mx = (tid < MMGRID) ? g_pmax[tid] : -FLT_MAX;
    #pragma unroll
    for (int o = 16; o > 0; o >>= 1) {
        mn = fminf(mn, __shfl_xor_sync(0xffffffffu, mn, o));
        mx = fmaxf(mx, __shfl_xor_sync(0xffffffffu, mx, o));
    }
    if (lane == 0) { s_red[wid] = mn; s_red[wid + BLK / 32] = mx; }
    __syncthreads();
    if (tid == 0) {
        s_bcast[0] = fminf(s_red[0], s_red[1]);          // warps 0,1 cover tid<64
        s_bcast[1] = fmaxf(s_red[BLK / 32], s_red[BLK / 32 + 1]);
    }
    __syncthreads();
    const float umin  = s_bcast[0];
    const float range = s_bcast[1] - umin;

    const int i = blockIdx.x * BLK + tid;
    if (i < n) {
        float unc = g_unc[i];
        float ca  = g_confacc[i];
        int acc   = (ca > 0.0f) ? 1 : 0;
        float conf = fabsf(ca);
        float w = acc ? conf : (1.0f - conf);
        float t = 1.0f - 2.0f / (__expf(2.0f * unc) + 1.0f);   // tanh(u), u>=0
        float bc = w * (1.0f - t);
        float bu = w * t;
        int j0 = 21;
        #pragma unroll
        for (int j = 20; j >= 0; j--) {
            float thv = umin + (0.05f * (float)j) * range;
            if (unc <= thv) j0 = j;
        }
        atomicAdd(&sb[acc * 44 + j0], bc);
        atomicAdd(&sb[acc * 44 + 22 + j0], bu);
    }
    __syncthreads();
    if (tid < 88) {
        float v = sb[tid];
        if (v != 0.0f) atomicAdd(&g_bins[tid], v);   // 88 spread addresses
    }

    // last-block election (monotonic counter; 2^32 % 256 == 0 -> replay-safe)
    __threadfence();
    if (tid == 0) {
        unsigned int d = atomicAdd(&g_done, 1u);
        is_last = (d % gridDim.x == gridDim.x - 1);
    }
    __syncthreads();
    if (!is_last) return;

    __shared__ float fb[88];
    __shared__ float s_cs;
    if (tid < 88) {
        fb[tid] = g_bins[tid];
        g_bins[tid] = 0.0f;                  // leave zeroed for next replay
    }
    if (tid == 0) {
        float cs = 0.0f;
        for (int b = 0; b < MMGRID; b++) cs += g_pce[b];
        s_cs = cs;
    }
    __syncthreads();

    if (tid == 0) {
        float au_rem = 0.0f, iu_rem = 0.0f;
        for (int k = 0; k < 22; k++) {
            au_rem += fb[66 + k];   // acc=1, kind=U
            iu_rem += fb[22 + k];   // acc=0, kind=U
        }
        float nac = 0.0f, nic = 0.0f;
        float avu[21];
        for (int j = 0; j < 21; j++) {
            nac    += fb[44 + j];   // acc=1, kind=C prefix
            nic    += fb[j];        // acc=0, kind=C prefix
            au_rem -= fb[66 + j];
            iu_rem -= fb[22 + j];
            avu[j] = (nac + iu_rem) / (nac + au_rem + nic + iu_rem + 1e-12f);
        }
        float auc = 0.0f;
        for (int j = 0; j < 20; j++) auc += (avu[j + 1] + avu[j]);
        auc *= 0.5f * 0.05f;
        out[0] = -3.0f * logf(auc + 1e-12f) + s_cs / (float)n;
    }
}

extern "C" void kernel_launch(void* const* d_in, const int* in_sizes, int n_in,
                              void* d_out, int out_size) {
    const float*     logits = (const float*)d_in[0];
    const long long* labels = (const long long*)d_in[1];
    int n = in_sizes[1];
    int C = in_sizes[0] / n;

    const int WPB = 8;
    if (C == 1000) {
        k_rows_spec<WPB><<<(n + WPB - 1) / WPB, WPB * 32>>>(logits, labels, n);
    } else {
        k_rows_gen<WPB><<<(n + WPB - 1) / WPB, WPB * 32>>>(logits, labels, C, n);
    }

    cudaLaunchAttribute pdl[1];
    pdl[0].id = cudaLaunchAttributeProgrammaticStreamSerialization;
    pdl[0].val.programmaticStreamSerializationAllowed = 1;

    {
        cudaLaunchConfig_t cfg = {};
        cfg.gridDim  = dim3(MMGRID, 1, 1);
        cfg.blockDim = dim3(256, 1, 1);
        cfg.attrs = pdl;
        cfg.numAttrs = 1;
        cudaLaunchKernelEx(&cfg, k_mm<256>, n);
    }
    {
        cudaLaunchConfig_t cfg = {};
        cfg.gridDim  = dim3((unsigned)((n + 255) / 256), 1, 1);
        cfg.blockDim = dim3(256, 1, 1);
        cfg.attrs = pdl;
        cfg.numAttrs = 1;
        cudaLaunchKernelEx(&cfg, k_bins<256>, (float*)d_out, n);
    }
}